// round 1
// baseline (speedup 1.0000x reference)
#include <cuda_runtime.h>
#include <cuda_fp16.h>
#include <cstdint>

// Problem constants
#define T_  128
#define B_  64
#define N_  24
#define D_  256
#define H_  8
#define F_  32
#define TB_ (T_ * B_)              // 8192
#define QKV_ELEMS (TB_ * H_ * N_ * F_)  // 50,331,648

// fp16 scratch for q, k, v in layout [tb][h][n][f]
__device__ __half g_q[QKV_ELEMS];
__device__ __half g_k[QKV_ELEMS];
__device__ __half g_v[QKV_ELEMS];

// ---------------------------------------------------------------------------
// Projection GEMM: C[r, j] = sum_d A[r, d] * W[j, d] + bias[j], stored fp16.
// MODE 0 (KV): r = tb*24+n over all 196608 rows, j in [0,512): j<256 -> K (Wk),
//              j>=256 -> V (Wv). MODE 1 (Q): r = tb (8192 rows), joint from
//              blockIdx.z, j in [0,256) with per-joint weight Wq[h, joint].
// Tile: 256(M) x 128(N) x 32(K-chunk), 512 threads, warp tile 64x32 via
// mma.sync.m16n8k16 f16->f32.
// ---------------------------------------------------------------------------
template<int MODE>
__global__ __launch_bounds__(512, 1)
void qkv_gemm_kernel(const float* __restrict__ X,
                     const float* __restrict__ Wk, const float* __restrict__ bk,
                     const float* __restrict__ Wv, const float* __restrict__ bv,
                     const float* __restrict__ Wq, const float* __restrict__ bq)
{
    const int ntile = blockIdx.x;               // 128-col tile
    const int mtile = blockIdx.y;               // 256-row tile
    const int joint = (MODE == 1) ? blockIdx.z : 0;

    __shared__ __half As[256][40];              // 32 K-cols + 8 pad
    __shared__ __half Bs[128][40];

    const int tid  = threadIdx.x;
    const int lane = tid & 31;
    const int warp = tid >> 5;                  // 16 warps
    const int wm   = warp >> 2;                 // 0..3  -> rows wm*64
    const int wn   = warp & 3;                  // 0..3  -> cols wn*32

    float C[4][4][4];
    #pragma unroll
    for (int a = 0; a < 4; a++)
        #pragma unroll
        for (int b = 0; b < 4; b++)
            #pragma unroll
            for (int c = 0; c < 4; c++) C[a][b][c] = 0.f;

    for (int kc = 0; kc < 256; kc += 32) {
        __syncthreads();   // protect previous iteration's reads

        // --- load A tile (256 x 32 fp32 -> fp16 smem) ---
        {
            const int r0 = tid >> 3;            // 0..63
            const int c4 = tid & 7;             // float4 index, 0..7
            #pragma unroll
            for (int p = 0; p < 4; p++) {
                const int r = p * 64 + r0;
                long arow;
                if (MODE == 0) {
                    arow = (long)(mtile * 256 + r) * 256;
                } else {
                    const int tb = mtile * 256 + r;
                    arow = (long)tb * (N_ * D_) + joint * D_;
                }
                const float4 v = *(const float4*)(X + arow + kc + c4 * 4);
                *(__half2*)&As[r][c4 * 4]     = __floats2half2_rn(v.x, v.y);
                *(__half2*)&As[r][c4 * 4 + 2] = __floats2half2_rn(v.z, v.w);
            }
        }
        // --- load B tile (128 x 32, weight rows are (j, d) i.e. K-major) ---
        {
            const int j0 = tid >> 3;
            const int c4 = tid & 7;
            #pragma unroll
            for (int p = 0; p < 2; p++) {
                const int j  = p * 64 + j0;
                const int jg = ntile * 128 + j;
                const float* wrow;
                if (MODE == 0) {
                    wrow = (jg < 256) ? (Wk + (long)jg * 256)
                                      : (Wv + (long)(jg - 256) * 256);
                } else {
                    const int h = jg >> 5, f = jg & 31;
                    wrow = Wq + (long)((h * N_ + joint) * F_ + f) * 256;
                }
                const float4 v = *(const float4*)(wrow + kc + c4 * 4);
                *(__half2*)&Bs[j][c4 * 4]     = __floats2half2_rn(v.x, v.y);
                *(__half2*)&Bs[j][c4 * 4 + 2] = __floats2half2_rn(v.z, v.w);
            }
        }
        __syncthreads();

        // --- 2 k-steps of 16 ---
        #pragma unroll
        for (int ks = 0; ks < 2; ks++) {
            const int acol = ks * 16 + (lane & 3) * 2;
            uint32_t a[4][4], b[4][2];
            const int ar = wm * 64 + (lane >> 2);
            #pragma unroll
            for (int mf = 0; mf < 4; mf++) {
                a[mf][0] = *(const uint32_t*)&As[ar + mf * 16][acol];
                a[mf][1] = *(const uint32_t*)&As[ar + mf * 16 + 8][acol];
                a[mf][2] = *(const uint32_t*)&As[ar + mf * 16][acol + 8];
                a[mf][3] = *(const uint32_t*)&As[ar + mf * 16 + 8][acol + 8];
            }
            const int br = wn * 32 + (lane >> 2);
            #pragma unroll
            for (int nf = 0; nf < 4; nf++) {
                b[nf][0] = *(const uint32_t*)&Bs[br + nf * 8][acol];
                b[nf][1] = *(const uint32_t*)&Bs[br + nf * 8][acol + 8];
            }
            #pragma unroll
            for (int mf = 0; mf < 4; mf++)
                #pragma unroll
                for (int nf = 0; nf < 4; nf++) {
                    float* c = C[mf][nf];
                    asm volatile(
                        "mma.sync.aligned.m16n8k16.row.col.f32.f16.f16.f32 "
                        "{%0,%1,%2,%3}, {%4,%5,%6,%7}, {%8,%9}, {%0,%1,%2,%3};\n"
                        : "+f"(c[0]), "+f"(c[1]), "+f"(c[2]), "+f"(c[3])
                        : "r"(a[mf][0]), "r"(a[mf][1]), "r"(a[mf][2]), "r"(a[mf][3]),
                          "r"(b[nf][0]), "r"(b[nf][1]));
                }
        }
    }

    // --- epilogue: bias add, fp16 store to [tb][h][n][f] scratch ---
    #pragma unroll
    for (int mf = 0; mf < 4; mf++) {
        #pragma unroll
        for (int nf = 0; nf < 4; nf++) {
            const float* c = C[mf][nf];
            const int lr = wm * 64 + mf * 16 + (lane >> 2);
            const int lc = wn * 32 + nf * 8 + (lane & 3) * 2;
            const int jg = ntile * 128 + lc;
            const int h  = jg >> 5;           // uniform within warp's 32-col band
            const int f  = jg & 31;
            #pragma unroll
            for (int rr = 0; rr < 2; rr++) {
                const int gr = mtile * 256 + lr + rr * 8;
                if (MODE == 0) {
                    const int tb = gr / 24;
                    const int n  = gr - tb * 24;
                    const float2 bb = (jg < 256) ? *(const float2*)(bk + jg)
                                                 : *(const float2*)(bv + jg - 256);
                    __half* dst = ((jg < 256) ? g_k : g_v)
                                  + ((long)((tb * H_ + (jg < 256 ? h : h - 8)) * N_ + n)) * F_ + f;
                    *(__half2*)dst = __floats2half2_rn(c[rr * 2] + bb.x,
                                                       c[rr * 2 + 1] + bb.y);
                } else {
                    const int tb = gr;
                    const int bi = (h * N_ + joint) * F_ + f;
                    const float2 bb = *(const float2*)(bq + bi);
                    __half* dst = g_q + ((long)((tb * H_ + h) * N_ + joint)) * F_ + f;
                    *(__half2*)dst = __floats2half2_rn(c[rr * 2] + bb.x,
                                                       c[rr * 2 + 1] + bb.y);
                }
            }
        }
    }
}

// ---------------------------------------------------------------------------
// Attention: one block per tb (8192 blocks), warp w = head h.
// smem per head: q (24x36 h), k (24x36 h), v (24x36 h); scores overlay q+k
// region as fp32 with stride 25 (bank-conflict-free softmax).
// ---------------------------------------------------------------------------
__global__ __launch_bounds__(256)
void attn_kernel(float* __restrict__ out)
{
    const int tb = blockIdx.x;
    __shared__ __half sm[8 * 2592];   // 41472 B

    const int tid = threadIdx.x;

    // Stage q, k, v for this tb: global per-tb slice is contiguous 6144 halves.
    {
        const __half2* gq = (const __half2*)(g_q + (long)tb * (H_ * N_ * F_));
        const __half2* gk = (const __half2*)(g_k + (long)tb * (H_ * N_ * F_));
        const __half2* gv = (const __half2*)(g_v + (long)tb * (H_ * N_ * F_));
        for (int p = tid; p < 3072; p += 256) {
            const int f2 = p & 15;              // half2 index within f
            const int n  = (p >> 4) % 24;
            const int h  = p / 384;
            const int dst = h * 2592 + n * 36 + f2 * 2;
            *(__half2*)&sm[dst]        = gq[p];
            *(__half2*)&sm[dst + 864]  = gk[p];
            *(__half2*)&sm[dst + 1728] = gv[p];
        }
    }
    __syncthreads();

    const int h = tid >> 5;
    const int l = tid & 31;
    const __half* q = sm + h * 2592;
    const __half* k = q + 864;
    const __half* v = q + 1728;

    // scores: 576 elements / 32 lanes = 18 each
    float sc[18];
    #pragma unroll
    for (int i = 0; i < 18; i++) {
        const int idx = i * 32 + l;
        const int n = idx / 24;
        const int m = idx - n * 24;
        const __half2* qr = (const __half2*)(q + n * 36);
        const __half2* kr = (const __half2*)(k + m * 36);
        float acc = 0.f;
        #pragma unroll
        for (int kk = 0; kk < 16; kk++) {
            const float2 qa = __half22float2(qr[kk]);
            const float2 kb = __half22float2(kr[kk]);
            acc = fmaf(qa.x, kb.x, acc);
            acc = fmaf(qa.y, kb.y, acc);
        }
        sc[i] = acc * 0.17677669529663687f;   // 1/sqrt(32)
    }
    __syncwarp();

    float* ss = (float*)(sm + h * 2592);      // overlays dead q+k (2400B <= 3456B)
    #pragma unroll
    for (int i = 0; i < 18; i++) {
        const int idx = i * 32 + l;
        const int n = idx / 24;
        ss[n * 25 + (idx - n * 24)] = sc[i];
    }
    __syncwarp();

    // softmax: lanes 0..23 each own one row
    if (l < 24) {
        float* row = ss + l * 25;
        float mx = row[0];
        #pragma unroll
        for (int m = 1; m < 24; m++) mx = fmaxf(mx, row[m]);
        float e[24];
        float sum = 0.f;
        #pragma unroll
        for (int m = 0; m < 24; m++) { e[m] = __expf(row[m] - mx); sum += e[m]; }
        const float inv = 1.f / sum;
        #pragma unroll
        for (int m = 0; m < 24; m++) row[m] = e[m] * inv;
    }
    __syncwarp();

    // out[n, f=lane] = sum_m attn[n, m] * v[m, lane]
    float vr[24];
    #pragma unroll
    for (int m = 0; m < 24; m++) vr[m] = __half2float(v[m * 36 + l]);

    float* o = out + (long)tb * (N_ * H_ * F_) + h * F_ + l;
    #pragma unroll
    for (int n = 0; n < 24; n++) {
        const float* ar = ss + n * 25;
        float acc = 0.f;
        #pragma unroll
        for (int m = 0; m < 24; m++) acc = fmaf(ar[m], vr[m], acc);
        o[n * 256] = acc;                      // [tb][n*256 + h*32 + f]
    }
}

// ---------------------------------------------------------------------------
extern "C" void kernel_launch(void* const* d_in, const int* in_sizes, int n_in,
                              void* d_out, int out_size)
{
    const float* X  = (const float*)d_in[0];
    const float* Wk = (const float*)d_in[1];
    const float* bk = (const float*)d_in[2];
    const float* Wv = (const float*)d_in[3];
    const float* bv = (const float*)d_in[4];
    const float* Wq = (const float*)d_in[5];
    const float* bq = (const float*)d_in[6];
    float* out = (float*)d_out;

    // KV projection: M = 196608, N = 512 -> grid (4 n-tiles, 768 m-tiles)
    qkv_gemm_kernel<0><<<dim3(4, 768, 1), 512>>>(X, Wk, bk, Wv, bv, Wq, bq);
    // Q projection: per joint, M = 8192, N = 256 -> grid (2, 32, 24)
    qkv_gemm_kernel<1><<<dim3(2, 32, 24), 512>>>(X, Wk, bk, Wv, bv, Wq, bq);
    // Attention + output
    attn_kernel<<<TB_, 256>>>(out);
}

// round 3
// speedup vs baseline: 1.1265x; 1.1265x over previous
#include <cuda_runtime.h>
#include <cuda_fp16.h>
#include <cstdint>

// Problem constants
#define T_  128
#define B_  64
#define N_  24
#define D_  256
#define H_  8
#define F_  32
#define TB_ 8192
#define ROWS_ (TB_ * N_)                 // 196608
#define QKV_ELEMS (TB_ * H_ * N_ * F_)   // 50,331,648

// fp16 scratch
__device__ __half g_q[QKV_ELEMS];        // [tb][h][n][f]
__device__ __half g_k[QKV_ELEMS];
__device__ __half g_v[QKV_ELEMS];
__device__ __half g_xh[ROWS_ * D_];      // [joint][tb][256]  (row r = joint*8192 + tb)
__device__ __half g_wkv[512 * 256];      // rows 0..255 Wk, 256..511 Wv
__device__ __half g_wq[24 * 256 * 256];  // [joint][h*32+f][256]

__device__ __forceinline__ void cp_async16(uint32_t dst, const void* src) {
    asm volatile("cp.async.cg.shared.global [%0], [%1], 16;\n" :: "r"(dst), "l"(src));
}

// ---------------------------------------------------------------------------
// Convert X (fp32 [tb][n][256]) -> g_xh (fp16 [n][tb][256])
// ---------------------------------------------------------------------------
__global__ __launch_bounds__(256)
void convert_x_kernel(const float* __restrict__ X)
{
    const int base = blockIdx.x * 2048 + threadIdx.x;   // float4 index
    #pragma unroll
    for (int i = 0; i < 8; i++) {
        const int g  = base + i * 256;       // < 12,582,912
        const int r  = g >> 6;               // dst row (joint*8192 + tb)
        const int c4 = g & 63;
        const int n  = r >> 13;
        const int tb = r & 8191;
        const float4 v = *(const float4*)(X + (((long)(tb * 24 + n)) * 64 + c4) * 4);
        __half2 h[2];
        h[0] = __floats2half2_rn(v.x, v.y);
        h[1] = __floats2half2_rn(v.z, v.w);
        *(uint2*)(g_xh + (long)r * 256 + c4 * 4) = *(uint2*)h;
    }
}

// ---------------------------------------------------------------------------
// Convert weights to fp16: g_wkv and per-joint-contiguous g_wq
// ---------------------------------------------------------------------------
__global__ __launch_bounds__(256)
void convert_w_kernel(const float* __restrict__ Wk, const float* __restrict__ Wv,
                      const float* __restrict__ Wq)
{
    const int g = blockIdx.x * 256 + threadIdx.x;       // float4 index
    if (g < 32768) {                                    // KV: 512 rows x 64 f4
        const int r = g >> 6, c4 = g & 63;
        const float* src = ((r < 256) ? Wk + r * 256 : Wv + (r - 256) * 256) + c4 * 4;
        const float4 v = *(const float4*)src;
        __half2 h[2];
        h[0] = __floats2half2_rn(v.x, v.y);
        h[1] = __floats2half2_rn(v.z, v.w);
        *(uint2*)(g_wkv + r * 256 + c4 * 4) = *(uint2*)h;
    } else {                                            // Q: 6144 rows x 64 f4
        const int gg = g - 32768;
        const int r = gg >> 6, c4 = gg & 63;            // r = joint*256 + h*32 + f
        const int joint = r >> 8, hf = r & 255;
        const int h = hf >> 5, f = hf & 31;
        const float4 v = *(const float4*)(Wq + (((h * 24 + joint) * 32 + f) * 64 + c4) * 4);
        __half2 hh[2];
        hh[0] = __floats2half2_rn(v.x, v.y);
        hh[1] = __floats2half2_rn(v.z, v.w);
        *(uint2*)(g_wq + r * 256 + c4 * 4) = *(uint2*)hh;
    }
}

// ---------------------------------------------------------------------------
// Fused projection GEMM: C[r, j] over M=196608 (r = joint*8192+tb),
// N=768 (j<256 K, <512 V, else Q with per-joint weights).
// Tile 256x128x32, 512 threads, cp.async 2-stage pipeline, mma.m16n8k16.
// ---------------------------------------------------------------------------
__global__ __launch_bounds__(512, 1)
void fused_gemm_kernel(const float* __restrict__ bk, const float* __restrict__ bv,
                       const float* __restrict__ bq)
{
    extern __shared__ __half sm[];
    // As: stage s at halves [s*10240, +10240)   (256 rows x stride 40)
    // Bs: stage s at halves [20480 + s*5120, +5120) (128 rows x stride 40)

    const int ntile = blockIdx.x;               // 0..5
    const int mtile = blockIdx.y;               // 0..767
    const int joint = mtile >> 5;               // tile is joint-uniform
    const int tid  = threadIdx.x;
    const int lane = tid & 31;
    const int warp = tid >> 5;
    const int wm   = warp >> 2;
    const int wn   = warp & 3;

    // --- load descriptors (fixed per thread) ---
    const int ar0  = tid >> 2;                  // A rows ar0 and ar0+128
    const int ak16 = tid & 3;
    const __half* asrc0 = g_xh + (long)(mtile * 256 + ar0) * 256 + ak16 * 8;
    const __half* asrc1 = asrc0 + 128 * 256;

    const int brow = tid >> 2;                  // B row (one per thread)
    const int bk16 = tid & 3;
    const int jg   = ntile * 128 + brow;
    const __half* bsrc = ((jg < 512) ? g_wkv + jg * 256
                                     : g_wq + (joint * 256 + (jg - 512)) * 256) + bk16 * 8;

    const uint32_t smem_base = (uint32_t)__cvta_generic_to_shared(sm);
    const uint32_t aDst0 = smem_base + (ar0 * 40 + ak16 * 8) * 2;
    const uint32_t aDst1 = aDst0 + 128 * 40 * 2;
    const uint32_t bDst  = smem_base + 40960 + (brow * 40 + bk16 * 8) * 2;

    float C[4][4][4];
    #pragma unroll
    for (int a = 0; a < 4; a++)
        #pragma unroll
        for (int b = 0; b < 4; b++)
            #pragma unroll
            for (int c = 0; c < 4; c++) C[a][b][c] = 0.f;

    // prologue: stage 0
    cp_async16(aDst0, asrc0);
    cp_async16(aDst1, asrc1);
    cp_async16(bDst,  bsrc);
    asm volatile("cp.async.commit_group;\n");

    #pragma unroll
    for (int it = 0; it < 8; it++) {
        if (it < 7) {
            const int s  = (it + 1) & 1;
            const int kc = (it + 1) * 32;
            cp_async16(aDst0 + s * 20480, asrc0 + kc);
            cp_async16(aDst1 + s * 20480, asrc1 + kc);
            cp_async16(bDst  + s * 10240, bsrc  + kc);
            asm volatile("cp.async.commit_group;\n");
            asm volatile("cp.async.wait_group 1;\n");
        } else {
            asm volatile("cp.async.wait_group 0;\n");
        }
        __syncthreads();

        const __half* Abase = sm + (it & 1) * 10240;
        const __half* Bbase = sm + 20480 + (it & 1) * 5120;

        #pragma unroll
        for (int ks = 0; ks < 2; ks++) {
            const int acol = ks * 16 + (lane & 3) * 2;
            uint32_t a[4][4], b[4][2];
            const int ar = wm * 64 + (lane >> 2);
            #pragma unroll
            for (int mf = 0; mf < 4; mf++) {
                a[mf][0] = *(const uint32_t*)&Abase[(ar + mf * 16)     * 40 + acol];
                a[mf][1] = *(const uint32_t*)&Abase[(ar + mf * 16 + 8) * 40 + acol];
                a[mf][2] = *(const uint32_t*)&Abase[(ar + mf * 16)     * 40 + acol + 8];
                a[mf][3] = *(const uint32_t*)&Abase[(ar + mf * 16 + 8) * 40 + acol + 8];
            }
            const int br = wn * 32 + (lane >> 2);
            #pragma unroll
            for (int nf = 0; nf < 4; nf++) {
                b[nf][0] = *(const uint32_t*)&Bbase[(br + nf * 8) * 40 + acol];
                b[nf][1] = *(const uint32_t*)&Bbase[(br + nf * 8) * 40 + acol + 8];
            }
            #pragma unroll
            for (int mf = 0; mf < 4; mf++)
                #pragma unroll
                for (int nf = 0; nf < 4; nf++) {
                    float* c = C[mf][nf];
                    asm volatile(
                        "mma.sync.aligned.m16n8k16.row.col.f32.f16.f16.f32 "
                        "{%0,%1,%2,%3}, {%4,%5,%6,%7}, {%8,%9}, {%0,%1,%2,%3};\n"
                        : "+f"(c[0]), "+f"(c[1]), "+f"(c[2]), "+f"(c[3])
                        : "r"(a[mf][0]), "r"(a[mf][1]), "r"(a[mf][2]), "r"(a[mf][3]),
                          "r"(b[nf][0]), "r"(b[nf][1]));
                }
        }
        __syncthreads();
    }

    // --- epilogue: block-uniform K/V/Q selection, bias add, fp16 store ---
    __half* dst_base = (ntile < 2) ? g_k : (ntile < 4) ? g_v : g_q;
    const int nsub = (ntile < 2) ? ntile : (ntile < 4) ? (ntile - 2) : (ntile - 4);

    #pragma unroll
    for (int mf = 0; mf < 4; mf++) {
        #pragma unroll
        for (int nf = 0; nf < 4; nf++) {
            const float* c = C[mf][nf];
            const int lr = wm * 64 + mf * 16 + (lane >> 2);
            const int lc = wn * 32 + nf * 8 + (lane & 3) * 2;
            const int j2 = nsub * 128 + lc;       // 0..255 within K/V/Q
            const int h  = j2 >> 5;
            const int f  = j2 & 31;
            float2 bb;
            if (ntile < 2)      bb = *(const float2*)(bk + j2);
            else if (ntile < 4) bb = *(const float2*)(bv + j2);
            else                bb = *(const float2*)(bq + (h * 24 + joint) * 32 + f);
            #pragma unroll
            for (int rr = 0; rr < 2; rr++) {
                const int r  = mtile * 256 + lr + rr * 8;
                const int tb = r & 8191;
                const int n  = r >> 13;           // == joint
                __half* dst = dst_base + ((long)((tb * H_ + h) * N_ + n)) * F_ + f;
                *(__half2*)dst = __floats2half2_rn(c[rr * 2] + bb.x,
                                                   c[rr * 2 + 1] + bb.y);
            }
        }
    }
}

// ---------------------------------------------------------------------------
// Attention: one block per tb, warp = head. (unchanged from passing R1)
// ---------------------------------------------------------------------------
__global__ __launch_bounds__(256)
void attn_kernel(float* __restrict__ out)
{
    const int tb = blockIdx.x;
    __shared__ __half sm[8 * 2592];

    const int tid = threadIdx.x;
    {
        const __half2* gq = (const __half2*)(g_q + (long)tb * (H_ * N_ * F_));
        const __half2* gk = (const __half2*)(g_k + (long)tb * (H_ * N_ * F_));
        const __half2* gv = (const __half2*)(g_v + (long)tb * (H_ * N_ * F_));
        for (int p = tid; p < 3072; p += 256) {
            const int f2 = p & 15;
            const int n  = (p >> 4) % 24;
            const int h  = p / 384;
            const int dst = h * 2592 + n * 36 + f2 * 2;
            *(__half2*)&sm[dst]        = gq[p];
            *(__half2*)&sm[dst + 864]  = gk[p];
            *(__half2*)&sm[dst + 1728] = gv[p];
        }
    }
    __syncthreads();

    const int h = tid >> 5;
    const int l = tid & 31;
    const __half* q = sm + h * 2592;
    const __half* k = q + 864;
    const __half* v = q + 1728;

    float sc[18];
    #pragma unroll
    for (int i = 0; i < 18; i++) {
        const int idx = i * 32 + l;
        const int n = idx / 24;
        const int m = idx - n * 24;
        const __half2* qr = (const __half2*)(q + n * 36);
        const __half2* kr = (const __half2*)(k + m * 36);
        float acc = 0.f;
        #pragma unroll
        for (int kk = 0; kk < 16; kk++) {
            const float2 qa = __half22float2(qr[kk]);
            const float2 kb = __half22float2(kr[kk]);
            acc = fmaf(qa.x, kb.x, acc);
            acc = fmaf(qa.y, kb.y, acc);
        }
        sc[i] = acc * 0.17677669529663687f;
    }
    __syncwarp();

    float* ss = (float*)(sm + h * 2592);
    #pragma unroll
    for (int i = 0; i < 18; i++) {
        const int idx = i * 32 + l;
        const int n = idx / 24;
        ss[n * 25 + (idx - n * 24)] = sc[i];
    }
    __syncwarp();

    if (l < 24) {
        float* row = ss + l * 25;
        float mx = row[0];
        #pragma unroll
        for (int m = 1; m < 24; m++) mx = fmaxf(mx, row[m]);
        float e[24];
        float sum = 0.f;
        #pragma unroll
        for (int m = 0; m < 24; m++) { e[m] = __expf(row[m] - mx); sum += e[m]; }
        const float inv = 1.f / sum;
        #pragma unroll
        for (int m = 0; m < 24; m++) row[m] = e[m] * inv;
    }
    __syncwarp();

    float vr[24];
    #pragma unroll
    for (int m = 0; m < 24; m++) vr[m] = __half2float(v[m * 36 + l]);

    float* o = out + (long)tb * (N_ * H_ * F_) + h * F_ + l;
    #pragma unroll
    for (int n = 0; n < 24; n++) {
        const float* ar = ss + n * 25;
        float acc = 0.f;
        #pragma unroll
        for (int m = 0; m < 24; m++) acc = fmaf(ar[m], vr[m], acc);
        o[n * 256] = acc;
    }
}

// ---------------------------------------------------------------------------
extern "C" void kernel_launch(void* const* d_in, const int* in_sizes, int n_in,
                              void* d_out, int out_size)
{
    const float* X  = (const float*)d_in[0];
    const float* Wk = (const float*)d_in[1];
    const float* bk = (const float*)d_in[2];
    const float* Wv = (const float*)d_in[3];
    const float* bv = (const float*)d_in[4];
    const float* Wq = (const float*)d_in[5];
    const float* bq = (const float*)d_in[6];
    float* out = (float*)d_out;

    cudaFuncSetAttribute(fused_gemm_kernel,
                         cudaFuncAttributeMaxDynamicSharedMemorySize, 61440);

    convert_x_kernel<<<6144, 256>>>(X);                 // 12.58M float4
    convert_w_kernel<<<1664, 256>>>(Wk, Wv, Wq);        // 425984 float4
    fused_gemm_kernel<<<dim3(6, 768, 1), 512, 61440>>>(bk, bv, bq);
    attn_kernel<<<TB_, 256>>>(out);
}

// round 6
// speedup vs baseline: 1.1720x; 1.0404x over previous
#include <cuda_runtime.h>
#include <cuda_fp16.h>
#include <cstdint>

// Problem constants
#define T_  128
#define B_  64
#define N_  24
#define D_  256
#define H_  8
#define F_  32
#define TB_ 8192
#define ROWS_ (TB_ * N_)                 // 196608
#define QKV_ELEMS (TB_ * H_ * N_ * F_)   // 50,331,648

// fp16 scratch
__device__ __half g_q[QKV_ELEMS];        // [tb][h][n][f]
__device__ __half g_k[QKV_ELEMS];
__device__ __half g_v[QKV_ELEMS];
__device__ __half g_xh[ROWS_ * D_];      // [joint][tb][256]  (row r = joint*8192 + tb)
__device__ __half g_wkv[512 * 256];      // rows 0..255 Wk, 256..511 Wv
__device__ __half g_wq[24 * 256 * 256];  // [joint][h*32+f][256]

__device__ __forceinline__ void cp_async16(uint32_t dst, const void* src) {
    asm volatile("cp.async.cg.shared.global [%0], [%1], 16;\n" :: "r"(dst), "l"(src));
}

// ---------------------------------------------------------------------------
// Convert X (fp32 [tb][n][256]) -> g_xh (fp16 [n][tb][256])
// ---------------------------------------------------------------------------
__global__ __launch_bounds__(256)
void convert_x_kernel(const float* __restrict__ X)
{
    const int base = blockIdx.x * 2048 + threadIdx.x;   // float4 index
    #pragma unroll
    for (int i = 0; i < 8; i++) {
        const int g  = base + i * 256;       // < 12,582,912
        const int r  = g >> 6;               // dst row (joint*8192 + tb)
        const int c4 = g & 63;
        const int n  = r >> 13;
        const int tb = r & 8191;
        const float4 v = *(const float4*)(X + (((long)(tb * 24 + n)) * 64 + c4) * 4);
        __half2 h[2];
        h[0] = __floats2half2_rn(v.x, v.y);
        h[1] = __floats2half2_rn(v.z, v.w);
        *(uint2*)(g_xh + (long)r * 256 + c4 * 4) = *(uint2*)h;
    }
}

// ---------------------------------------------------------------------------
// Convert weights to fp16: g_wkv and per-joint-contiguous g_wq
// ---------------------------------------------------------------------------
__global__ __launch_bounds__(256)
void convert_w_kernel(const float* __restrict__ Wk, const float* __restrict__ Wv,
                      const float* __restrict__ Wq)
{
    const int g = blockIdx.x * 256 + threadIdx.x;       // float4 index
    if (g < 32768) {                                    // KV: 512 rows x 64 f4
        const int r = g >> 6, c4 = g & 63;
        const float* src = ((r < 256) ? Wk + r * 256 : Wv + (r - 256) * 256) + c4 * 4;
        const float4 v = *(const float4*)src;
        __half2 h[2];
        h[0] = __floats2half2_rn(v.x, v.y);
        h[1] = __floats2half2_rn(v.z, v.w);
        *(uint2*)(g_wkv + r * 256 + c4 * 4) = *(uint2*)h;
    } else {                                            // Q: 6144 rows x 64 f4
        const int gg = g - 32768;
        const int r = gg >> 6, c4 = gg & 63;            // r = joint*256 + h*32 + f
        const int joint = r >> 8, hf = r & 255;
        const int h = hf >> 5, f = hf & 31;
        const float4 v = *(const float4*)(Wq + (((h * 24 + joint) * 32 + f) * 64 + c4) * 4);
        __half2 hh[2];
        hh[0] = __floats2half2_rn(v.x, v.y);
        hh[1] = __floats2half2_rn(v.z, v.w);
        *(uint2*)(g_wq + r * 256 + c4 * 4) = *(uint2*)hh;
    }
}

// ---------------------------------------------------------------------------
// Fused projection GEMM: C[r, j] over M=196608 (r = joint*8192+tb),
// N=768 (j<256 K, <512 V, else Q with per-joint weights).
// Tile 256x128x32, 512 threads, cp.async 3-stage pipeline (1 sync/iter),
// mma.m16n8k16.
// Stage layout (bytes): A [0,20480) rows 0-255, B [20480,30720); stage
// stride 30720 B; 3 stages = 92160 B dynamic smem.
// ---------------------------------------------------------------------------
__global__ __launch_bounds__(512, 1)
void fused_gemm_kernel(const float* __restrict__ bk, const float* __restrict__ bv,
                       const float* __restrict__ bq)
{
    extern __shared__ __half sm[];

    const int ntile = blockIdx.x;               // 0..5
    const int mtile = blockIdx.y;               // 0..767
    const int joint = mtile >> 5;               // tile is joint-uniform
    const int tid  = threadIdx.x;
    const int lane = tid & 31;
    const int warp = tid >> 5;
    const int wm   = warp >> 2;
    const int wn   = warp & 3;

    // --- load descriptors (fixed per thread) ---
    const int ar0  = tid >> 2;                  // A rows ar0 and ar0+128
    const int ak16 = tid & 3;
    const __half* asrc0 = g_xh + (long)(mtile * 256 + ar0) * 256 + ak16 * 8;
    const __half* asrc1 = asrc0 + 128 * 256;

    const int brow = tid >> 2;                  // B row (one per thread)
    const int bk16 = tid & 3;
    const int jg   = ntile * 128 + brow;
    const __half* bsrc = ((jg < 512) ? g_wkv + jg * 256
                                     : g_wq + (joint * 256 + (jg - 512)) * 256) + bk16 * 8;

    const uint32_t smem_base = (uint32_t)__cvta_generic_to_shared(sm);
    const uint32_t aDst = smem_base + (ar0 * 40 + ak16 * 8) * 2;
    const uint32_t bDst = smem_base + 20480 + (brow * 40 + bk16 * 8) * 2;

    float C[4][4][4];
    #pragma unroll
    for (int a = 0; a < 4; a++)
        #pragma unroll
        for (int b = 0; b < 4; b++)
            #pragma unroll
            for (int c = 0; c < 4; c++) C[a][b][c] = 0.f;

    // prologue: chunks 0,1 into stages 0,1
    #pragma unroll
    for (int c = 0; c < 2; c++) {
        const uint32_t so = c * 30720;
        cp_async16(aDst + so,         asrc0 + c * 32);
        cp_async16(aDst + so + 10240, asrc1 + c * 32);
        cp_async16(bDst + so,         bsrc  + c * 32);
        asm volatile("cp.async.commit_group;\n");
    }

    #pragma unroll
    for (int it = 0; it < 8; it++) {
        if (it < 7) asm volatile("cp.async.wait_group 1;\n");
        else        asm volatile("cp.async.wait_group 0;\n");
        __syncthreads();

        // issue chunk it+2 into slot (it+2)%3 (freed by compute of it-1)
        if (it + 2 < 8) {
            const int c = it + 2;
            const uint32_t so = (c % 3) * 30720;
            cp_async16(aDst + so,         asrc0 + c * 32);
            cp_async16(aDst + so + 10240, asrc1 + c * 32);
            cp_async16(bDst + so,         bsrc  + c * 32);
            asm volatile("cp.async.commit_group;\n");
        }

        const __half* Abase = sm + (it % 3) * 15360;
        const __half* Bbase = Abase + 10240;

        #pragma unroll
        for (int ks = 0; ks < 2; ks++) {
            const int acol = ks * 16 + (lane & 3) * 2;
            uint32_t a[4][4], b[4][2];
            const int ar = wm * 64 + (lane >> 2);
            #pragma unroll
            for (int mf = 0; mf < 4; mf++) {
                a[mf][0] = *(const uint32_t*)&Abase[(ar + mf * 16)     * 40 + acol];
                a[mf][1] = *(const uint32_t*)&Abase[(ar + mf * 16 + 8) * 40 + acol];
                a[mf][2] = *(const uint32_t*)&Abase[(ar + mf * 16)     * 40 + acol + 8];
                a[mf][3] = *(const uint32_t*)&Abase[(ar + mf * 16 + 8) * 40 + acol + 8];
            }
            const int br = wn * 32 + (lane >> 2);
            #pragma unroll
            for (int nf = 0; nf < 4; nf++) {
                b[nf][0] = *(const uint32_t*)&Bbase[(br + nf * 8) * 40 + acol];
                b[nf][1] = *(const uint32_t*)&Bbase[(br + nf * 8) * 40 + acol + 8];
            }
            #pragma unroll
            for (int mf = 0; mf < 4; mf++)
                #pragma unroll
                for (int nf = 0; nf < 4; nf++) {
                    float* c = C[mf][nf];
                    asm volatile(
                        "mma.sync.aligned.m16n8k16.row.col.f32.f16.f16.f32 "
                        "{%0,%1,%2,%3}, {%4,%5,%6,%7}, {%8,%9}, {%0,%1,%2,%3};\n"
                        : "+f"(c[0]), "+f"(c[1]), "+f"(c[2]), "+f"(c[3])
                        : "r"(a[mf][0]), "r"(a[mf][1]), "r"(a[mf][2]), "r"(a[mf][3]),
                          "r"(b[nf][0]), "r"(b[nf][1]));
                }
        }
    }

    // --- epilogue: block-uniform K/V/Q selection, bias add, fp16 store ---
    __half* dst_base = (ntile < 2) ? g_k : (ntile < 4) ? g_v : g_q;
    const int nsub = (ntile < 2) ? ntile : (ntile < 4) ? (ntile - 2) : (ntile - 4);

    #pragma unroll
    for (int mf = 0; mf < 4; mf++) {
        #pragma unroll
        for (int nf = 0; nf < 4; nf++) {
            const float* c = C[mf][nf];
            const int lr = wm * 64 + mf * 16 + (lane >> 2);
            const int lc = wn * 32 + nf * 8 + (lane & 3) * 2;
            const int j2 = nsub * 128 + lc;       // 0..255 within K/V/Q
            const int h  = j2 >> 5;
            const int f  = j2 & 31;
            float2 bb;
            if (ntile < 2)      bb = *(const float2*)(bk + j2);
            else if (ntile < 4) bb = *(const float2*)(bv + j2);
            else                bb = *(const float2*)(bq + (h * 24 + joint) * 32 + f);
            #pragma unroll
            for (int rr = 0; rr < 2; rr++) {
                const int r  = mtile * 256 + lr + rr * 8;
                const int tb = r & 8191;
                const int n  = r >> 13;           // == joint
                __half* dst = dst_base + ((long)((tb * H_ + h) * N_ + n)) * F_ + f;
                *(__half2*)dst = __floats2half2_rn(c[rr * 2] + bb.x,
                                                   c[rr * 2 + 1] + bb.y);
            }
        }
    }
}

// ---------------------------------------------------------------------------
// Attention: one block per tb, warp = head. Vectorized LDS.128 version.
// Per head (halves, stride 40 per row): q [0,960), k [960,1920), v [1920,2880).
// Head stride 2880 halves (5760 B). Scores/probs overlay q+k as fp32 rows of
// stride 28 (112 B, 16B-aligned), written only after q/k fully consumed.
// ---------------------------------------------------------------------------
__global__ __launch_bounds__(256)
void attn_kernel(float* __restrict__ out)
{
    const int tb = blockIdx.x;
    __shared__ __align__(16) __half sm[8 * 2880];   // 23040 halves = 46080 B

    const int tid = threadIdx.x;

    // Stage q, k, v: 6144 halves per tensor per tb = 768 uint4 -> 3 iterations
    {
        const uint4* gq = (const uint4*)(g_q + (long)tb * (H_ * N_ * F_));
        const uint4* gk = (const uint4*)(g_k + (long)tb * (H_ * N_ * F_));
        const uint4* gv = (const uint4*)(g_v + (long)tb * (H_ * N_ * F_));
        #pragma unroll
        for (int i = 0; i < 3; i++) {
            const int p  = tid + i * 256;        // < 768
            const int f4 = p & 3;                // 4 uint4 per 32-half row
            const int n  = (p >> 2) % 24;
            const int h  = p / 96;               // < 8
            const int dst = h * 2880 + n * 40 + f4 * 8;
            *(uint4*)&sm[dst]        = gq[p];
            *(uint4*)&sm[dst + 960]  = gk[p];
            *(uint4*)&sm[dst + 1920] = gv[p];
        }
    }
    __syncthreads();

    const int h = tid >> 5;
    const int l = tid & 31;
    const __half* q = sm + h * 2880;
    const __half* k = q + 960;
    const __half* v = q + 1920;

    // scores: 576 elements / 32 lanes = 18 each, vector loads
    float sc[18];
    #pragma unroll
    for (int i = 0; i < 18; i++) {
        const int idx = i * 32 + l;
        const int n = idx / 24;
        const int m = idx - n * 24;
        const uint4* qr = (const uint4*)(q + n * 40);
        const uint4* kr = (const uint4*)(k + m * 40);
        float acc = 0.f;
        #pragma unroll
        for (int c = 0; c < 4; c++) {
            const uint4 qv = qr[c];
            const uint4 kv = kr[c];
            const __half2* qh = (const __half2*)&qv;
            const __half2* kh = (const __half2*)&kv;
            #pragma unroll
            for (int j = 0; j < 4; j++) {
                const float2 qa = __half22float2(qh[j]);
                const float2 kb = __half22float2(kh[j]);
                acc = fmaf(qa.x, kb.x, acc);
                acc = fmaf(qa.y, kb.y, acc);
            }
        }
        sc[i] = acc * 0.17677669529663687f;   // 1/sqrt(32)
    }
    __syncwarp();   // all lanes done reading q/k before overlay writes

    float* ss = (float*)(sm + h * 2880);      // overlays q+k (2668 B <= 3840 B)
    #pragma unroll
    for (int i = 0; i < 18; i++) {
        const int idx = i * 32 + l;
        const int n = idx / 24;
        ss[n * 28 + (idx - n * 24)] = sc[i];
    }
    __syncwarp();

    // softmax: lanes 0..23 own one row each, vectorized row access
    if (l < 24) {
        float4 r4[6];
        float* rv = (float*)r4;
        const float4* row = (const float4*)(ss + l * 28);
        #pragma unroll
        for (int i = 0; i < 6; i++) r4[i] = row[i];
        float mx = rv[0];
        #pragma unroll
        for (int m = 1; m < 24; m++) mx = fmaxf(mx, rv[m]);
        float sum = 0.f;
        #pragma unroll
        for (int m = 0; m < 24; m++) { rv[m] = __expf(rv[m] - mx); sum += rv[m]; }
        const float inv = 1.f / sum;
        #pragma unroll
        for (int m = 0; m < 24; m++) rv[m] *= inv;
        float4* roww = (float4*)(ss + l * 28);
        #pragma unroll
        for (int i = 0; i < 6; i++) roww[i] = r4[i];
    }
    __syncwarp();

    // out[n, f=lane] = sum_m attn[n, m] * v[m, lane]
    float vr[24];
    #pragma unroll
    for (int m = 0; m < 24; m++) vr[m] = __half2float(v[m * 40 + l]);

    float* o = out + (long)tb * (N_ * H_ * F_) + h * F_ + l;
    #pragma unroll
    for (int n = 0; n < 24; n++) {
        const float4* pr = (const float4*)(ss + n * 28);   // broadcast
        float acc = 0.f;
        #pragma unroll
        for (int c = 0; c < 6; c++) {
            const float4 p4 = pr[c];
            acc = fmaf(p4.x, vr[c * 4],     acc);
            acc = fmaf(p4.y, vr[c * 4 + 1], acc);
            acc = fmaf(p4.z, vr[c * 4 + 2], acc);
            acc = fmaf(p4.w, vr[c * 4 + 3], acc);
        }
        o[n * 256] = acc;                      // [tb][n*256 + h*32 + f]
    }
}

// ---------------------------------------------------------------------------
extern "C" void kernel_launch(void* const* d_in, const int* in_sizes, int n_in,
                              void* d_out, int out_size)
{
    const float* X  = (const float*)d_in[0];
    const float* Wk = (const float*)d_in[1];
    const float* bk = (const float*)d_in[2];
    const float* Wv = (const float*)d_in[3];
    const float* bv = (const float*)d_in[4];
    const float* Wq = (const float*)d_in[5];
    const float* bq = (const float*)d_in[6];
    float* out = (float*)d_out;

    cudaFuncSetAttribute(fused_gemm_kernel,
                         cudaFuncAttributeMaxDynamicSharedMemorySize, 92160);

    convert_x_kernel<<<6144, 256>>>(X);                 // 12.58M float4
    convert_w_kernel<<<1664, 256>>>(Wk, Wv, Wq);        // 425984 float4
    fused_gemm_kernel<<<dim3(6, 768, 1), 512, 92160>>>(bk, bv, bq);
    attn_kernel<<<TB_, 256>>>(out);
}